// round 9
// baseline (speedup 1.0000x reference)
#include <cuda_runtime.h>
#include <cuda_fp16.h>
#include <cstdint>
#include <cstddef>

// Problem dims (fixed by the dataset)
#define BB 8
#define TC 2048
#define TQ 1024
#define DD 1024

// ---------------- scratch (allocation-free: __device__ globals) ----------------
__device__ __align__(256) __half g_attn[(size_t)BB * TC * TQ];  // fp16 softmax probs, 32 MiB
__device__ __align__(256) __half g_qt[(size_t)BB * DD * TQ];    // fp16 qencode^T [b][d][q], 16 MiB

// ---------------- helpers ----------------
__device__ __forceinline__ uint32_t smem_u32(const void* p) {
    uint32_t a;
    asm("{ .reg .u64 t; cvta.to.shared.u64 t, %1; cvt.u32.u64 %0, t; }" : "=r"(a) : "l"(p));
    return a;
}
__device__ __forceinline__ void cp_async16(uint32_t s, const void* g) {
    asm volatile("cp.async.cg.shared.global [%0], [%1], 16;" :: "r"(s), "l"(g) : "memory");
}
__device__ __forceinline__ void cp_commit() {
    asm volatile("cp.async.commit_group;" ::: "memory");
}
template <int N>
__device__ __forceinline__ void cp_wait() {
    asm volatile("cp.async.wait_group %0;" :: "n"(N) : "memory");
}
__device__ __forceinline__ void ldsm_x4(uint32_t& r0, uint32_t& r1, uint32_t& r2, uint32_t& r3,
                                        uint32_t addr) {
    asm volatile("ldmatrix.sync.aligned.m8n8.x4.shared.b16 {%0,%1,%2,%3}, [%4];"
                 : "=r"(r0), "=r"(r1), "=r"(r2), "=r"(r3) : "r"(addr));
}
// m16n8k16 fp16 MMA, fp32 accumulate
__device__ __forceinline__ void mma_f16(float& c0, float& c1, float& c2, float& c3,
                                        uint32_t a0, uint32_t a1, uint32_t a2, uint32_t a3,
                                        uint32_t b0, uint32_t b1) {
    asm volatile(
        "mma.sync.aligned.m16n8k16.row.col.f32.f16.f16.f32 "
        "{%0,%1,%2,%3}, {%4,%5,%6,%7}, {%8,%9}, {%0,%1,%2,%3};"
        : "+f"(c0), "+f"(c1), "+f"(c2), "+f"(c3)
        : "r"(a0), "r"(a1), "r"(a2), "r"(a3), "r"(b0), "r"(b1));
}

// ---------------- kernel 1: merged preprocessing ----------------
// blocks [0, 2048): softmax, warp-per-row, 8 rows/block
// blocks [2048, 10240): transpose+fp16 convert of qencode (32x32 tiles)
static constexpr int N_SOFTMAX_BLOCKS = BB * TC / 8;                    // 2048
static constexpr int N_TRANSPOSE_BLOCKS = (DD / 32) * (TQ / 32) * BB;   // 8192

__global__ __launch_bounds__(256) void pre_kernel(const float* __restrict__ sim,
                                                  const float* __restrict__ q) {
    const int bid = blockIdx.x;
    const int tid = threadIdx.x;

    if (bid < N_SOFTMAX_BLOCKS) {
        // ---- softmax path (warp per row, no smem/sync) ----
        const int warp = tid >> 5;
        const int lane = tid & 31;
        const size_t row = (size_t)bid * 8 + warp;

        const float4* in = reinterpret_cast<const float4*>(sim + row * TQ);
        float4 v[8];
        #pragma unroll
        for (int j = 0; j < 8; j++) v[j] = in[lane + 32 * j];

        float m = -1e30f;
        #pragma unroll
        for (int j = 0; j < 8; j++)
            m = fmaxf(m, fmaxf(fmaxf(v[j].x, v[j].y), fmaxf(v[j].z, v[j].w)));
        #pragma unroll
        for (int o = 16; o > 0; o >>= 1) m = fmaxf(m, __shfl_xor_sync(0xFFFFFFFFu, m, o));

        float sum = 0.f;
        #pragma unroll
        for (int j = 0; j < 8; j++) {
            v[j].x = __expf(v[j].x - m); v[j].y = __expf(v[j].y - m);
            v[j].z = __expf(v[j].z - m); v[j].w = __expf(v[j].w - m);
            sum += (v[j].x + v[j].y) + (v[j].z + v[j].w);
        }
        #pragma unroll
        for (int o = 16; o > 0; o >>= 1) sum += __shfl_xor_sync(0xFFFFFFFFu, sum, o);
        const float inv = 1.0f / sum;

        uint2* orow = reinterpret_cast<uint2*>(g_attn + row * TQ);
        #pragma unroll
        for (int j = 0; j < 8; j++) {
            __half2 h01 = __floats2half2_rn(v[j].x * inv, v[j].y * inv);
            __half2 h23 = __floats2half2_rn(v[j].z * inv, v[j].w * inv);
            uint2 pk;
            pk.x = *reinterpret_cast<uint32_t*>(&h01);
            pk.y = *reinterpret_cast<uint32_t*>(&h23);
            orow[lane + 32 * j] = pk;
        }
    } else {
        // ---- transpose path ----
        __shared__ float tile[32][33];
        const int t = bid - N_SOFTMAX_BLOCKS;
        const int dt = t & 31;
        const int qt = (t >> 5) & 31;
        const int b = t >> 10;
        const int tx = tid & 31;
        const int ty = tid >> 5;
        const float* src = q + (size_t)b * TQ * DD;
        #pragma unroll
        for (int i = 0; i < 4; i++) {
            int qq = qt * 32 + ty + i * 8;
            tile[ty + i * 8][tx] = src[(size_t)qq * DD + dt * 32 + tx];
        }
        __syncthreads();
        __half* dst = g_qt + (size_t)b * DD * TQ;
        #pragma unroll
        for (int i = 0; i < 4; i++) {
            int d2 = dt * 32 + ty + i * 8;
            dst[(size_t)d2 * TQ + qt * 32 + tx] = __float2half_rn(tile[tx][ty + i * 8]);
        }
    }
}

// ---------------- kernel 2: FP16 mma.sync GEMM, CTA 256x128, 512 threads, 4 stages ----------------
// C[b, c, d] = sum_q A[b,c,q] * Bt[b,d,q]   (both operands K-major fp16)
// 16 warps (4 M x 4 N), warp tile 64x32, KC=64 halves, 4-stage cp.async pipeline, 1 CTA/SM.
static constexpr int TM = 256;
static constexpr int TN = 128;
static constexpr int KC = 64;
static constexpr int NCH = TQ / KC;              // 16 k-chunks
static constexpr int SROW = 72;                  // smem row stride (halves): conflict-free for ldmatrix
static constexpr int A_BYTES = TM * SROW * 2;    // 36864
static constexpr int B_BYTES = TN * SROW * 2;    // 18432
static constexpr int STAGE_BYTES = A_BYTES + B_BYTES;   // 55296
static constexpr int STAGES = 4;
static constexpr int SMEM_BYTES = STAGES * STAGE_BYTES; // 221184 <= 227KB

__global__ __launch_bounds__(512, 1) void gemm_f16_kernel(float* __restrict__ out) {
    extern __shared__ __half smem[];
    const int tid = threadIdx.x;
    const int wid = tid >> 5, lane = tid & 31;
    const int g = lane >> 2, t = lane & 3;          // mma groupID / threadID-in-group
    const int wm = (wid & 3) * 64;                  // warp m offset within CTA tile (4 warps over 256)
    const int wn = (wid >> 2) * 32;                 // warp n offset within CTA tile (4 warps over 128)
    const int dtile = blockIdx.x, ctile = blockIdx.y, b = blockIdx.z;

    const __half* Ag = g_attn + ((size_t)b * TC + (size_t)ctile * TM) * TQ;
    const __half* Bg = g_qt + ((size_t)b * DD + (size_t)dtile * TN) * TQ;

    const uint32_t smem_base = smem_u32(smem);

    // cp.async addressing: 512 threads; A = 256 rows x 4 chunks(16B), B = 128 rows x 4 chunks
    const int f_row0 = tid >> 3;            // 0..63
    const int f_ch = tid & 7;               // 16B chunk within row (8 chunks of 8 halves = 64)

    auto fetch = [&](int kc, int stg) {
        uint32_t sa = smem_base + (uint32_t)(stg * STAGE_BYTES);
        uint32_t sb = sa + (uint32_t)A_BYTES;
        #pragma unroll
        for (int i = 0; i < 4; i++) {
            int row = f_row0 + i * 64;
            cp_async16(sa + (uint32_t)(row * SROW + f_ch * 8) * 2u,
                       Ag + (size_t)row * TQ + kc * KC + f_ch * 8);
        }
        #pragma unroll
        for (int i = 0; i < 2; i++) {
            int row = f_row0 + i * 64;
            cp_async16(sb + (uint32_t)(row * SROW + f_ch * 8) * 2u,
                       Bg + (size_t)row * TQ + kc * KC + f_ch * 8);
        }
    };

    // ldmatrix per-lane addressing (precomputed)
    const int a_row = wm + (lane & 15);                   // + i*16
    const int a_col = (lane >> 4) * 8;                    // + k0
    const int b_row = wn + (lane & 7) + (lane >> 4) * 8;  // + j2*16
    const int b_col = ((lane >> 3) & 1) * 8;              // + k0

    float acc[4][4][4];
    #pragma unroll
    for (int i = 0; i < 4; i++)
        #pragma unroll
        for (int j = 0; j < 4; j++)
            #pragma unroll
            for (int r = 0; r < 4; r++) acc[i][j][r] = 0.f;

    fetch(0, 0); cp_commit();
    fetch(1, 1); cp_commit();
    fetch(2, 2); cp_commit();

    for (int kc = 0; kc < NCH; kc++) {
        cp_wait<STAGES - 2>();
        __syncthreads();

        if (kc + 3 < NCH) fetch(kc + 3, (kc + 3) & (STAGES - 1));
        cp_commit();

        const int stg = kc & (STAGES - 1);
        const uint32_t sA = smem_base + (uint32_t)(stg * STAGE_BYTES);
        const uint32_t sB = sA + (uint32_t)A_BYTES;

        #pragma unroll
        for (int ks = 0; ks < 4; ks++) {
            const int k0 = ks * 16;
            uint32_t af[4][4], bf[4][2];
            #pragma unroll
            for (int i = 0; i < 4; i++)
                ldsm_x4(af[i][0], af[i][1], af[i][2], af[i][3],
                        sA + (uint32_t)((a_row + i * 16) * SROW + k0 + a_col) * 2u);
            #pragma unroll
            for (int j2 = 0; j2 < 2; j2++)
                ldsm_x4(bf[j2 * 2][0], bf[j2 * 2][1], bf[j2 * 2 + 1][0], bf[j2 * 2 + 1][1],
                        sB + (uint32_t)((b_row + j2 * 16) * SROW + k0 + b_col) * 2u);
            #pragma unroll
            for (int i = 0; i < 4; i++)
                #pragma unroll
                for (int j = 0; j < 4; j++)
                    mma_f16(acc[i][j][0], acc[i][j][1], acc[i][j][2], acc[i][j][3],
                            af[i][0], af[i][1], af[i][2], af[i][3],
                            bf[j][0], bf[j][1]);
        }
    }
    cp_wait<0>();

    // epilogue: direct global stores (float2 per fragment pair)
    const size_t orow0 = (size_t)b * TC + ctile * TM + wm + g;
    const int col0 = dtile * TN + wn + t * 2;
    #pragma unroll
    for (int i = 0; i < 4; i++) {
        float* p0 = out + (orow0 + i * 16) * DD + col0;
        float* p1 = p0 + 8 * DD;
        #pragma unroll
        for (int j = 0; j < 4; j++) {
            *reinterpret_cast<float2*>(p0 + j * 8) = make_float2(acc[i][j][0], acc[i][j][1]);
            *reinterpret_cast<float2*>(p1 + j * 8) = make_float2(acc[i][j][2], acc[i][j][3]);
        }
    }
}

// ---------------- launcher ----------------
extern "C" void kernel_launch(void* const* d_in, const int* in_sizes, int n_in,
                              void* d_out, int out_size) {
    const float* sim  = (const float*)d_in[0];   // [8, 2048, 1024] fp32
    const float* qenc = (const float*)d_in[1];   // [8, 1024, 1024] fp32
    float* out = (float*)d_out;                  // [8, 2048, 1024] fp32

    cudaFuncSetAttribute(gemm_f16_kernel, cudaFuncAttributeMaxDynamicSharedMemorySize, SMEM_BYTES);

    pre_kernel<<<N_SOFTMAX_BLOCKS + N_TRANSPOSE_BLOCKS, 256>>>(sim, qenc);
    gemm_f16_kernel<<<dim3(DD / TN, TC / TM, BB), 512, SMEM_BYTES>>>(out);
}

// round 11
// speedup vs baseline: 1.0588x; 1.0588x over previous
#include <cuda_runtime.h>
#include <cuda_fp16.h>
#include <cstdint>
#include <cstddef>

// Problem dims (fixed by the dataset)
#define BB 8
#define TC 2048
#define TQ 1024
#define DD 1024

// ---------------- scratch (allocation-free: __device__ globals) ----------------
__device__ __align__(256) __half g_attn[(size_t)BB * TC * TQ];  // fp16 softmax probs, 32 MiB
__device__ __align__(256) __half g_qt[(size_t)BB * DD * TQ];    // fp16 qencode^T [b][d][q], 16 MiB

// ---------------- helpers ----------------
__device__ __forceinline__ uint32_t smem_u32(const void* p) {
    uint32_t a;
    asm("{ .reg .u64 t; cvta.to.shared.u64 t, %1; cvt.u32.u64 %0, t; }" : "=r"(a) : "l"(p));
    return a;
}
__device__ __forceinline__ void cp_async16(uint32_t s, const void* g) {
    asm volatile("cp.async.cg.shared.global [%0], [%1], 16;" :: "r"(s), "l"(g) : "memory");
}
__device__ __forceinline__ void cp_commit() {
    asm volatile("cp.async.commit_group;" ::: "memory");
}
template <int N>
__device__ __forceinline__ void cp_wait() {
    asm volatile("cp.async.wait_group %0;" :: "n"(N) : "memory");
}
__device__ __forceinline__ void ldsm_x4(uint32_t& r0, uint32_t& r1, uint32_t& r2, uint32_t& r3,
                                        uint32_t addr) {
    asm volatile("ldmatrix.sync.aligned.m8n8.x4.shared.b16 {%0,%1,%2,%3}, [%4];"
                 : "=r"(r0), "=r"(r1), "=r"(r2), "=r"(r3) : "r"(addr));
}
// m16n8k16 fp16 MMA, fp32 accumulate
__device__ __forceinline__ void mma_f16(float& c0, float& c1, float& c2, float& c3,
                                        uint32_t a0, uint32_t a1, uint32_t a2, uint32_t a3,
                                        uint32_t b0, uint32_t b1) {
    asm volatile(
        "mma.sync.aligned.m16n8k16.row.col.f32.f16.f16.f32 "
        "{%0,%1,%2,%3}, {%4,%5,%6,%7}, {%8,%9}, {%0,%1,%2,%3};"
        : "+f"(c0), "+f"(c1), "+f"(c2), "+f"(c3)
        : "r"(a0), "r"(a1), "r"(a2), "r"(a3), "r"(b0), "r"(b1));
}

// ---------------- kernel 1: merged preprocessing ----------------
// blocks [0, 2048): softmax, warp-per-row, 8 rows/block
// blocks [2048, 10240): transpose+fp16 convert of qencode (32x32 tiles)
static constexpr int N_SOFTMAX_BLOCKS = BB * TC / 8;                    // 2048
static constexpr int N_TRANSPOSE_BLOCKS = (DD / 32) * (TQ / 32) * BB;   // 8192

__global__ __launch_bounds__(256) void pre_kernel(const float* __restrict__ sim,
                                                  const float* __restrict__ q) {
    const int bid = blockIdx.x;
    const int tid = threadIdx.x;

    if (bid < N_SOFTMAX_BLOCKS) {
        // ---- softmax path (warp per row, no smem/sync) ----
        const int warp = tid >> 5;
        const int lane = tid & 31;
        const size_t row = (size_t)bid * 8 + warp;

        const float4* in = reinterpret_cast<const float4*>(sim + row * TQ);
        float4 v[8];
        #pragma unroll
        for (int j = 0; j < 8; j++) v[j] = in[lane + 32 * j];

        float m = -1e30f;
        #pragma unroll
        for (int j = 0; j < 8; j++)
            m = fmaxf(m, fmaxf(fmaxf(v[j].x, v[j].y), fmaxf(v[j].z, v[j].w)));
        #pragma unroll
        for (int o = 16; o > 0; o >>= 1) m = fmaxf(m, __shfl_xor_sync(0xFFFFFFFFu, m, o));

        float sum = 0.f;
        #pragma unroll
        for (int j = 0; j < 8; j++) {
            v[j].x = __expf(v[j].x - m); v[j].y = __expf(v[j].y - m);
            v[j].z = __expf(v[j].z - m); v[j].w = __expf(v[j].w - m);
            sum += (v[j].x + v[j].y) + (v[j].z + v[j].w);
        }
        #pragma unroll
        for (int o = 16; o > 0; o >>= 1) sum += __shfl_xor_sync(0xFFFFFFFFu, sum, o);
        const float inv = 1.0f / sum;

        uint2* orow = reinterpret_cast<uint2*>(g_attn + row * TQ);
        #pragma unroll
        for (int j = 0; j < 8; j++) {
            __half2 h01 = __floats2half2_rn(v[j].x * inv, v[j].y * inv);
            __half2 h23 = __floats2half2_rn(v[j].z * inv, v[j].w * inv);
            uint2 pk;
            pk.x = *reinterpret_cast<uint32_t*>(&h01);
            pk.y = *reinterpret_cast<uint32_t*>(&h23);
            orow[lane + 32 * j] = pk;
        }
    } else {
        // ---- transpose path ----
        __shared__ float tile[32][33];
        const int t = bid - N_SOFTMAX_BLOCKS;
        const int dt = t & 31;
        const int qt = (t >> 5) & 31;
        const int b = t >> 10;
        const int tx = tid & 31;
        const int ty = tid >> 5;
        const float* src = q + (size_t)b * TQ * DD;
        #pragma unroll
        for (int i = 0; i < 4; i++) {
            int qq = qt * 32 + ty + i * 8;
            tile[ty + i * 8][tx] = src[(size_t)qq * DD + dt * 32 + tx];
        }
        __syncthreads();
        __half* dst = g_qt + (size_t)b * DD * TQ;
        #pragma unroll
        for (int i = 0; i < 4; i++) {
            int d2 = dt * 32 + ty + i * 8;
            dst[(size_t)d2 * TQ + qt * 32 + tx] = __float2half_rn(tile[tx][ty + i * 8]);
        }
    }
}

// ---------------- kernel 2: FP16 mma.sync GEMM, CTA 128x128, KC=32, 5-stage pipeline ----------------
// C[b, c, d] = sum_q A[b,c,q] * Bt[b,d,q]   (both operands K-major fp16)
// 8 warps (2 M x 4 N), warp tile 64x32, 2 CTAs/SM.
static constexpr int KC = 32;
static constexpr int NCH = TQ / KC;              // 32 k-chunks
static constexpr int SROW = 40;                  // smem row stride (halves): conflict-free for ldmatrix
static constexpr int A_HALVES = 128 * SROW;      // 5120
static constexpr int A_BYTES = A_HALVES * 2;     // 10240
static constexpr int STAGE_BYTES = 2 * A_BYTES;  // 20480 (A + B)
static constexpr int STAGES = 5;
static constexpr int SMEM_BYTES = STAGES * STAGE_BYTES;  // 102400 (x2 CTAs = 204800 <= 227KB)

__global__ __launch_bounds__(256, 2) void gemm_f16_kernel(float* __restrict__ out) {
    extern __shared__ __half smem[];
    const int tid = threadIdx.x;
    const int wid = tid >> 5, lane = tid & 31;
    const int g = lane >> 2, t = lane & 3;          // mma groupID / threadID-in-group
    const int wm = (wid & 1) * 64;                  // warp m offset within CTA tile
    const int wn = (wid >> 1) * 32;                 // warp n offset within CTA tile
    const int dtile = blockIdx.x, ctile = blockIdx.y, b = blockIdx.z;

    const __half* Ag = g_attn + ((size_t)b * TC + (size_t)ctile * 128) * TQ;
    const __half* Bg = g_qt + ((size_t)b * DD + (size_t)dtile * 128) * TQ;

    const uint32_t smem_base = smem_u32(smem);

    // cp.async addressing: tile = 128 rows x 32 halves = 4 x 16B chunks/row = 512 chunks/operand.
    // 256 threads x 2 row-iterations x 1 chunk = 512 chunks per operand.
    const int f_row0 = tid >> 2;            // 0..63, +64 on second iteration
    const int f_ch = tid & 3;               // 16B chunk within row (4 chunks of 8 halves)

    auto fetch = [&](int kc, int stg) {
        uint32_t sa = smem_base + (uint32_t)(stg * STAGE_BYTES);
        uint32_t sb = sa + (uint32_t)A_BYTES;
        #pragma unroll
        for (int i = 0; i < 2; i++) {
            int row = f_row0 + i * 64;
            uint32_t so = (uint32_t)(row * SROW + f_ch * 8) * 2u;
            cp_async16(sa + so, Ag + (size_t)row * TQ + kc * KC + f_ch * 8);
            cp_async16(sb + so, Bg + (size_t)row * TQ + kc * KC + f_ch * 8);
        }
    };

    // ldmatrix per-lane addressing (precomputed)
    const int a_row = wm + (lane & 15);             // + i*16
    const int a_col = (lane >> 4) * 8;              // + k0
    const int b_row = wn + (lane & 7) + (lane >> 4) * 8;  // + j2*16
    const int b_col = ((lane >> 3) & 1) * 8;        // + k0

    float acc[4][4][4];
    #pragma unroll
    for (int i = 0; i < 4; i++)
        #pragma unroll
        for (int j = 0; j < 4; j++)
            #pragma unroll
            for (int r = 0; r < 4; r++) acc[i][j][r] = 0.f;

    #pragma unroll
    for (int s = 0; s < STAGES - 1; s++) { fetch(s, s); cp_commit(); }

    for (int kc = 0; kc < NCH; kc++) {
        cp_wait<STAGES - 2>();
        __syncthreads();

        if (kc + STAGES - 1 < NCH) fetch(kc + STAGES - 1, (kc + STAGES - 1) % STAGES);
        cp_commit();

        const int stg = kc % STAGES;
        const uint32_t sA = smem_base + (uint32_t)(stg * STAGE_BYTES);
        const uint32_t sB = sA + (uint32_t)A_BYTES;

        #pragma unroll
        for (int ks = 0; ks < 2; ks++) {
            const int k0 = ks * 16;
            uint32_t af[4][4], bf[4][2];
            #pragma unroll
            for (int i = 0; i < 4; i++)
                ldsm_x4(af[i][0], af[i][1], af[i][2], af[i][3],
                        sA + (uint32_t)((a_row + i * 16) * SROW + k0 + a_col) * 2u);
            #pragma unroll
            for (int j2 = 0; j2 < 2; j2++)
                ldsm_x4(bf[j2 * 2][0], bf[j2 * 2][1], bf[j2 * 2 + 1][0], bf[j2 * 2 + 1][1],
                        sB + (uint32_t)((b_row + j2 * 16) * SROW + k0 + b_col) * 2u);
            #pragma unroll
            for (int i = 0; i < 4; i++)
                #pragma unroll
                for (int j = 0; j < 4; j++)
                    mma_f16(acc[i][j][0], acc[i][j][1], acc[i][j][2], acc[i][j][3],
                            af[i][0], af[i][1], af[i][2], af[i][3],
                            bf[j][0], bf[j][1]);
        }
    }
    cp_wait<0>();

    // epilogue: direct global stores (float2 per fragment pair)
    const size_t orow0 = (size_t)b * TC + ctile * 128 + wm + g;
    const int col0 = dtile * 128 + wn + t * 2;
    #pragma unroll
    for (int i = 0; i < 4; i++) {
        float* p0 = out + (orow0 + i * 16) * DD + col0;
        float* p1 = p0 + 8 * DD;
        #pragma unroll
        for (int j = 0; j < 4; j++) {
            *reinterpret_cast<float2*>(p0 + j * 8) = make_float2(acc[i][j][0], acc[i][j][1]);
            *reinterpret_cast<float2*>(p1 + j * 8) = make_float2(acc[i][j][2], acc[i][j][3]);
        }
    }
}

// ---------------- launcher ----------------
extern "C" void kernel_launch(void* const* d_in, const int* in_sizes, int n_in,
                              void* d_out, int out_size) {
    const float* sim  = (const float*)d_in[0];   // [8, 2048, 1024] fp32
    const float* qenc = (const float*)d_in[1];   // [8, 1024, 1024] fp32
    float* out = (float*)d_out;                  // [8, 2048, 1024] fp32

    cudaFuncSetAttribute(gemm_f16_kernel, cudaFuncAttributeMaxDynamicSharedMemorySize, SMEM_BYTES);

    pre_kernel<<<N_SOFTMAX_BLOCKS + N_TRANSPOSE_BLOCKS, 256>>>(sim, qenc);
    gemm_f16_kernel<<<dim3(DD / 128, TC / 128, BB), 256, SMEM_BYTES>>>(out);
}